// round 11
// baseline (speedup 1.0000x reference)
#include <cuda_runtime.h>
#include <cuda_fp16.h>
#include <math.h>
#include <stdint.h>

#define S   256
#define Hd  512
#define E   64
#define R   32
#define L   9
#define BMAX 1024
#define KSPLIT 8

typedef unsigned long long u64;

// Scratch (device globals; no allocation allowed)
__device__ float  g_H[4 * BMAX * Hd];      // tanh(x@W1+b1) for {e0, r0, r1, r2}
__device__ float  g_e02[KSPLIT * BMAX * E];     // split-K partials of e0
__device__ float  g_r2[KSPLIT * 3 * BMAX * R];  // split-K partials of r
__device__ __half g_A1h[(size_t)BMAX * E * E];  // A1[b][e][f] fp16
__device__ __half g_A2h[(size_t)BMAX * E * E];  // A2[b][e][f] fp16
__device__ float  g_v1p[(size_t)BMAX * 4 * E];  // per-quarter partials of v1

// ---------------------------------------------------------------------------
// Packed f32x2 helpers (Blackwell FFMA2)
// ---------------------------------------------------------------------------
__device__ __forceinline__ u64 pk2(float x, float y) {
    u64 r;
    asm("mov.b64 %0, {%1, %2};" : "=l"(r) : "f"(x), "f"(y));
    return r;
}
__device__ __forceinline__ void fma2(u64& d, u64 a, u64 b) {
    asm("fma.rn.f32x2 %0, %1, %2, %0;" : "+l"(d) : "l"(a), "l"(b));
}
__device__ __forceinline__ u64 mul2(u64 a, u64 b) {
    u64 d;
    asm("mul.rn.f32x2 %0, %1, %2;" : "=l"(d) : "l"(a), "l"(b));
    return d;
}
__device__ __forceinline__ float2 upk(u64 v) {
    float2 f;
    asm("mov.b64 {%0, %1}, %2;" : "=f"(f.x), "=f"(f.y) : "l"(v));
    return f;
}

// ---------------------------------------------------------------------------
// Tensor-core helpers
// ---------------------------------------------------------------------------
__device__ __forceinline__ void ldsm4(uint32_t& r0, uint32_t& r1,
                                      uint32_t& r2, uint32_t& r3, uint32_t a) {
    asm volatile("ldmatrix.sync.aligned.m8n8.x4.shared.b16 {%0,%1,%2,%3},[%4];"
                 : "=r"(r0), "=r"(r1), "=r"(r2), "=r"(r3) : "r"(a));
}
__device__ __forceinline__ void ldsm4t(uint32_t& r0, uint32_t& r1,
                                       uint32_t& r2, uint32_t& r3, uint32_t a) {
    asm volatile("ldmatrix.sync.aligned.m8n8.x4.trans.shared.b16 {%0,%1,%2,%3},[%4];"
                 : "=r"(r0), "=r"(r1), "=r"(r2), "=r"(r3) : "r"(a));
}
__device__ __forceinline__ void mma16816(float* c,
    uint32_t a0, uint32_t a1, uint32_t a2, uint32_t a3,
    uint32_t b0, uint32_t b1) {
    asm volatile(
        "mma.sync.aligned.m16n8k16.row.col.f32.f16.f16.f32 "
        "{%0,%1,%2,%3},{%4,%5,%6,%7},{%8,%9},{%0,%1,%2,%3};"
        : "+f"(c[0]), "+f"(c[1]), "+f"(c[2]), "+f"(c[3])
        : "r"(a0), "r"(a1), "r"(a2), "r"(a3), "r"(b0), "r"(b1));
}

// ---------------------------------------------------------------------------
// Kernel 1: H = tanh(x @ W1 + b1) via fp16 tensor cores, fp32 accumulate.
// PROVEN round-10 config (~13us): 64x64 CTA tile, 128 threads, K-chunk 32,
// double-buffered half smem.
// ---------------------------------------------------------------------------
__global__ __launch_bounds__(128) void k1_gemm_tanh(
    const float* __restrict__ x,
    const float* __restrict__ eW1, const float* __restrict__ eb1,
    const float* __restrict__ rW1, const float* __restrict__ rb1,
    int B)
{
    const int bn = blockIdx.x;
    const int bm = blockIdx.y;
    const int m  = bn >> 3;
    const int cb = (bn & 7) * 64;
    const float* W    = (m == 0) ? eW1 : (rW1 + (size_t)(m - 1) * S * Hd);
    const float* bias = (m == 0) ? eb1 : (rb1 + (size_t)(m - 1) * Hd);

    constexpr int AST = 40;
    constexpr int BST = 72;
    __shared__ __half Asm[2][64 * AST];
    __shared__ __half Bsm[2][32 * BST];

    const int tid  = threadIdx.x;
    const int warp = tid >> 5;
    const int lane = tid & 31;
    const int rowBase = bm * 64;
    const int warpM   = warp * 16;

    float acc[8][4];
    #pragma unroll
    for (int j = 0; j < 8; j++)
        #pragma unroll
        for (int i = 0; i < 4; i++) acc[j][i] = 0.0f;

    const uint32_t smA[2] = {
        (uint32_t)__cvta_generic_to_shared(&Asm[0][0]),
        (uint32_t)__cvta_generic_to_shared(&Asm[1][0]) };
    const uint32_t smB[2] = {
        (uint32_t)__cvta_generic_to_shared(&Bsm[0][0]),
        (uint32_t)__cvta_generic_to_shared(&Bsm[1][0]) };

    const int a_frow = warpM + (lane & 7) + ((lane >> 3) & 1) * 8;
    const int a_fcol = (lane >> 4) << 3;
    const int b_frow = (lane & 7) + ((lane >> 3) & 1) * 8;
    const int b_fcol = (lane >> 4) << 3;

    float4 av[4], wv[4];
    #pragma unroll
    for (int i = 0; i < 4; i++) {
        int t = tid + i * 128;
        av[i] = *(const float4*)&x[(size_t)(rowBase + (t >> 3)) * S + (t & 7) * 4];
        wv[i] = *(const float4*)&W[(size_t)(t >> 4) * Hd + cb + (t & 15) * 4];
    }
    int buf = 0;
    #pragma unroll
    for (int i = 0; i < 4; i++) {
        int t = tid + i * 128;
        __half2 ha0 = __floats2half2_rn(av[i].x, av[i].y);
        __half2 ha1 = __floats2half2_rn(av[i].z, av[i].w);
        uint2 ua; ua.x = *(uint32_t*)&ha0; ua.y = *(uint32_t*)&ha1;
        *(uint2*)&Asm[0][(t >> 3) * AST + (t & 7) * 4] = ua;
        __half2 hb0 = __floats2half2_rn(wv[i].x, wv[i].y);
        __half2 hb1 = __floats2half2_rn(wv[i].z, wv[i].w);
        uint2 ub; ub.x = *(uint32_t*)&hb0; ub.y = *(uint32_t*)&hb1;
        *(uint2*)&Bsm[0][(t >> 4) * BST + (t & 15) * 4] = ub;
    }
    __syncthreads();

    for (int c = 0; c < 8; c++) {
        if (c < 7) {
            const int k0 = (c + 1) * 32;
            #pragma unroll
            for (int i = 0; i < 4; i++) {
                int t = tid + i * 128;
                av[i] = *(const float4*)&x[(size_t)(rowBase + (t >> 3)) * S + k0 + (t & 7) * 4];
                wv[i] = *(const float4*)&W[(size_t)(k0 + (t >> 4)) * Hd + cb + (t & 15) * 4];
            }
        }
        #pragma unroll
        for (int kk = 0; kk < 32; kk += 16) {
            uint32_t a0, a1, a2, a3;
            ldsm4(a0, a1, a2, a3,
                  smA[buf] + (uint32_t)((a_frow * AST + kk + a_fcol) * 2));
            #pragma unroll
            for (int j = 0; j < 4; j++) {
                uint32_t b0, b1, b2, b3;
                ldsm4t(b0, b1, b2, b3,
                       smB[buf] + (uint32_t)(((kk + b_frow) * BST + j * 16 + b_fcol) * 2));
                mma16816(acc[2 * j],     a0, a1, a2, a3, b0, b1);
                mma16816(acc[2 * j + 1], a0, a1, a2, a3, b2, b3);
            }
        }
        if (c < 7) {
            const int nb = buf ^ 1;
            #pragma unroll
            for (int i = 0; i < 4; i++) {
                int t = tid + i * 128;
                __half2 ha0 = __floats2half2_rn(av[i].x, av[i].y);
                __half2 ha1 = __floats2half2_rn(av[i].z, av[i].w);
                uint2 ua; ua.x = *(uint32_t*)&ha0; ua.y = *(uint32_t*)&ha1;
                *(uint2*)&Asm[nb][(t >> 3) * AST + (t & 7) * 4] = ua;
                __half2 hb0 = __floats2half2_rn(wv[i].x, wv[i].y);
                __half2 hb1 = __floats2half2_rn(wv[i].z, wv[i].w);
                uint2 ub; ub.x = *(uint32_t*)&hb0; ub.y = *(uint32_t*)&hb1;
                *(uint2*)&Bsm[nb][(t >> 4) * BST + (t & 15) * 4] = ub;
            }
            __syncthreads();
            buf = nb;
        }
    }

    const int gid = lane >> 2, tig = lane & 3;
    const int r0 = rowBase + warpM + gid;
    #pragma unroll
    for (int j = 0; j < 8; j++) {
        const int col = cb + j * 8 + tig * 2;
        const float b0v = bias[col], b1v = bias[col + 1];
        float2 o0 = make_float2(tanhf(acc[j][0] + b0v), tanhf(acc[j][1] + b1v));
        float2 o1 = make_float2(tanhf(acc[j][2] + b0v), tanhf(acc[j][3] + b1v));
        *(float2*)&g_H[((size_t)m * B + r0)     * Hd + col] = o0;
        *(float2*)&g_H[((size_t)m * B + r0 + 8) * Hd + col] = o1;
    }
}

// ---------------------------------------------------------------------------
// Kernel 2: layer2 GEMM with split-K 8 (chunks of 64). 1024 CTAs for latency
// hiding on this skinny GEMM. Partials summed in k3a/k3b loaders.
// ---------------------------------------------------------------------------
template<int O>
__device__ __forceinline__ void k2_body(
    const float* __restrict__ Hb, const float* __restrict__ W2,
    const float* __restrict__ bias, float* __restrict__ outp,
    int B, int kbeg, float* sm)
{
    constexpr int TX = O / 4;
    constexpr int RT = 32 * TX / 256;
    float* Hs = sm;
    float* Ws = sm + 32 * 36;

    const int tid = threadIdx.x;
    const int rowBase = blockIdx.x * 32;
    const int tx = tid % TX;
    const int ty = tid / TX;

    const int h_row = tid >> 3;
    const int h_q   = tid & 7;

    float acc[RT][4];
    #pragma unroll
    for (int i = 0; i < RT; i++)
        #pragma unroll
        for (int j = 0; j < 4; j++) acc[i][j] = 0.0f;

    for (int k0 = kbeg; k0 < kbeg + (Hd / KSPLIT); k0 += 32) {
        float4 hv = *(const float4*)&Hb[(size_t)(rowBase + h_row) * Hd + k0 + h_q * 4];
        float4 wv[2];
        #pragma unroll
        for (int it = 0; it < (8 * O) / 256; it++) {
            int i = tid + it * 256;
            int k  = i / TX;
            int n4 = i % TX;
            wv[it] = *(const float4*)&W2[(size_t)(k0 + k) * O + n4 * 4];
        }
        __syncthreads();
        Hs[(h_q * 4 + 0) * 36 + h_row] = hv.x;
        Hs[(h_q * 4 + 1) * 36 + h_row] = hv.y;
        Hs[(h_q * 4 + 2) * 36 + h_row] = hv.z;
        Hs[(h_q * 4 + 3) * 36 + h_row] = hv.w;
        #pragma unroll
        for (int it = 0; it < (8 * O) / 256; it++) {
            int i = tid + it * 256;
            int k  = i / TX;
            int n4 = i % TX;
            *(float4*)&Ws[k * (O + 4) + n4 * 4] = wv[it];
        }
        __syncthreads();
        #pragma unroll
        for (int kk = 0; kk < 32; kk++) {
            float a[RT];
            #pragma unroll
            for (int i = 0; i < RT; i++) a[i] = Hs[kk * 36 + ty * RT + i];
            float4 w = *(const float4*)&Ws[kk * (O + 4) + tx * 4];
            #pragma unroll
            for (int i = 0; i < RT; i++) {
                acc[i][0] += a[i] * w.x;
                acc[i][1] += a[i] * w.y;
                acc[i][2] += a[i] * w.z;
                acc[i][3] += a[i] * w.w;
            }
        }
    }

    float bv[4];
    #pragma unroll
    for (int j = 0; j < 4; j++) bv[j] = bias ? bias[tx * 4 + j] : 0.0f;
    #pragma unroll
    for (int i = 0; i < RT; i++) {
        int row = rowBase + ty * RT + i;
        #pragma unroll
        for (int j = 0; j < 4; j++)
            outp[(size_t)row * O + tx * 4 + j] = acc[i][j] + bv[j];
    }
}

__global__ __launch_bounds__(256) void k2_all(
    const float* __restrict__ eW2, const float* __restrict__ eb2,
    const float* __restrict__ rW2, const float* __restrict__ rb2, int B)
{
    extern __shared__ float sm2[];
    const int kz   = blockIdx.z;
    const int kbeg = kz * (Hd / KSPLIT);
    if (blockIdx.y == 0) {
        k2_body<64>(g_H, eW2, kz ? nullptr : eb2,
                    g_e02 + (size_t)kz * B * E, B, kbeg, sm2);
    } else {
        int km = blockIdx.y - 1;
        k2_body<32>(g_H + (size_t)(1 + km) * B * Hd,
                    rW2 + (size_t)km * Hd * R, kz ? nullptr : (rb2 + km * R),
                    g_r2 + ((size_t)kz * 3 + km) * B * R,
                    B, kbeg, sm2);
    }
}

// ---------------------------------------------------------------------------
// Kernel 3a: streaming contraction (proven ~6.6 TB/s config). One CTA per
// (batch, e-quarter of 16), 256 threads, buf[8].
// ---------------------------------------------------------------------------
__global__ __launch_bounds__(256) void k3a_contract(
    const float* __restrict__ tpr, int B)
{
    __shared__ float2 srv2[96];
    __shared__ float  se0[16];
    __shared__ float  stmp[8 * 64];

    const int b = blockIdx.x >> 2;
    const int q = blockIdx.x & 3;
    const int tid = threadIdx.x;

    if (tid < 96) {
        const int k = tid >> 5, j = tid & 31;
        float v = 0.0f;
        #pragma unroll
        for (int kz = 0; kz < KSPLIT; kz++)
            v += g_r2[(((size_t)kz * 3 + k) * B + b) * R + j];
        srv2[tid] = make_float2(v, v);
    }
    if (tid < 16) {
        int e = q * 16 + tid;
        float v = 0.0f;
        #pragma unroll
        for (int kz = 0; kz < KSPLIT; kz++)
            v += g_e02[((size_t)kz * B + b) * E + e];
        se0[tid] = v;
    }
    __syncthreads();

    const int el = tid >> 4;
    const int e  = q * 16 + el;
    const int f4 = tid & 15;
    const float4* p = (const float4*)tpr + ((size_t)b * E + e) * (R * 16) + f4;
    const u64 pe = pk2(se0[el], se0[el]);

    u64 v01 = 0, v23 = 0, a10 = 0, a11 = 0, a20 = 0, a21 = 0;
    #pragma unroll 1
    for (int rb = 0; rb < 4; rb++) {
        float4 buf[8];
        #pragma unroll
        for (int u = 0; u < 8; u++)
            buf[u] = __ldcs(&p[(size_t)(rb * 8 + u) * 16]);
        #pragma unroll
        for (int u = 0; u < 8; u++) {
            const int r = rb * 8 + u;
            u64 t01 = pk2(buf[u].x, buf[u].y);
            u64 t23 = pk2(buf[u].z, buf[u].w);
            u64 c0 = *(u64*)&srv2[r];
            u64 c1 = *(u64*)&srv2[32 + r];
            u64 c2 = *(u64*)&srv2[64 + r];
            u64 ce = mul2(pe, c0);
            fma2(v01, ce, t01); fma2(v23, ce, t23);
            fma2(a10, c1, t01); fma2(a11, c1, t23);
            fma2(a20, c2, t01); fma2(a21, c2, t23);
        }
    }

    {
        __half2 h0 = __float22half2_rn(upk(a10));
        __half2 h1 = __float22half2_rn(upk(a11));
        *(__half2*)&g_A1h[(size_t)b * E * E + e * E + f4 * 4]     = h0;
        *(__half2*)&g_A1h[(size_t)b * E * E + e * E + f4 * 4 + 2] = h1;
        h0 = __float22half2_rn(upk(a20));
        h1 = __float22half2_rn(upk(a21));
        *(__half2*)&g_A2h[(size_t)b * E * E + e * E + f4 * 4]     = h0;
        *(__half2*)&g_A2h[(size_t)b * E * E + e * E + f4 * 4 + 2] = h1;
    }

    {
        float2 a = upk(v01), c = upk(v23);
        a.x += __shfl_xor_sync(0xffffffffu, a.x, 16);
        a.y += __shfl_xor_sync(0xffffffffu, a.y, 16);
        c.x += __shfl_xor_sync(0xffffffffu, c.x, 16);
        c.y += __shfl_xor_sync(0xffffffffu, c.y, 16);
        if ((tid & 31) < 16) {
            const int w = tid >> 5;
            *(float4*)&stmp[w * 64 + (tid & 15) * 4] = make_float4(a.x, a.y, c.x, c.y);
        }
    }
    __syncthreads();
    if (tid < 64) {
        float s = 0.0f;
        #pragma unroll
        for (int w = 0; w < 8; w++) s += stmp[w * 64 + tid];
        g_v1p[((size_t)b * 4 + q) * E + tid] = s;
    }
}

// ---------------------------------------------------------------------------
// Kernel 3b: chain, 64 threads per batch (2 warps). e-dimension split across
// warps (halves serial MACs); x broadcast via smem; LN in warp 0; Z epilogue
// as 9 parallel smem dots. All combine orders fixed -> deterministic.
// ---------------------------------------------------------------------------
__global__ __launch_bounds__(64) void k3b_chain(
    const float* __restrict__ ln_g, const float* __restrict__ ln_b,
    const float* __restrict__ Z,
    float* __restrict__ out, int B)
{
    __shared__ float sx[64];        // current chain vector
    __shared__ float sp[2][64];     // per-warp dot partials
    __shared__ float ssum[64];      // step_sum

    const int b   = blockIdx.x;
    const int tid = threadIdx.x;
    const int w   = tid >> 5;
    const int l   = tid & 31;
    const int f0  = 2 * l;

    const __half* A1 = g_A1h + (size_t)b * E * E;
    const __half* A2 = g_A2h + (size_t)b * E * E;

    // ---- step 0: i1 = LN(v1) ----
    if (w == 0) {
        float x0 = 0.0f, x1 = 0.0f;
        #pragma unroll
        for (int q = 0; q < 4; q++) {
            float2 v = *(const float2*)&g_v1p[((size_t)b * 4 + q) * E + f0];
            x0 += v.x; x1 += v.y;
        }
        float s1 = x0 + x1, s2 = x0 * x0 + x1 * x1;
        #pragma unroll
        for (int o = 16; o; o >>= 1) {
            s1 += __shfl_xor_sync(0xffffffffu, s1, o);
            s2 += __shfl_xor_sync(0xffffffffu, s2, o);
        }
        float mu  = s1 * (1.0f / 64.0f);
        float var = s2 * (1.0f / 64.0f) - mu * mu;
        float inv = rsqrtf(var + 1e-6f);
        float y0 = ln_g[f0]     * (x0 - mu) * inv + ln_b[f0];
        float y1 = ln_g[f0 + 1] * (x1 - mu) * inv + ln_b[f0 + 1];
        sx[f0] = y0; sx[f0 + 1] = y1;
        ssum[f0] = y0; ssum[f0 + 1] = y1;
    }
    __syncthreads();

    // ---- steps 1,2 ----
    #pragma unroll
    for (int step = 1; step < 3; step++) {
        const __half* A = (step == 1) ? A1 : A2;
        float a0 = 0.0f, a1 = 0.0f;
        #pragma unroll
        for (int i = 0; i < 32; i++) {
            const int e = w * 32 + i;
            float c = sx[e];
            float2 wv = __half22float2(*(const __half2*)&A[e * E + f0]);
            a0 += c * wv.x;
            a1 += c * wv.y;
        }
        sp[w][f0] = a0; sp[w][f0 + 1] = a1;
        __syncthreads();
        if (w == 0) {
            float v0  = sp[0][f0]     + sp[1][f0];
            float v1v = sp[0][f0 + 1] + sp[1][f0 + 1];
            float s1 = v0 + v1v, s2 = v0 * v0 + v1v * v1v;
            #pragma unroll
            for (int o = 16; o; o >>= 1) {
                s1 += __shfl_xor_sync(0xffffffffu, s1, o);
                s2 += __shfl_xor_sync(0xffffffffu, s2, o);
            }
            float mu  = s1 * (1.0f / 64.0f);
            float var = s2 * (1.0f / 64.0f) - mu * mu;
            float inv = rsqrtf(var + 1e-6f);
            float y0 = ln_g[step * E + f0]     * (v0  - mu) * inv + ln_b[step * E + f0];
            float y1 = ln_g[step * E + f0 + 1] * (v1v - mu) * inv + ln_b[step * E + f0 + 1];
            sx[f0] = y0; sx[f0 + 1] = y1;
            ssum[f0] += y0; ssum[f0 + 1] += y1;
        }
        __syncthreads();
    }

    // ---- out[b,:] = step_sum @ Z : 9 parallel dots over smem ----
    if (tid < L) {
        float acc = 0.0f;
        #pragma unroll 16
        for (int f = 0; f < E; f++) acc += ssum[f] * Z[f * L + tid];
        out[(size_t)b * L + tid] = acc;
    }
}

// ---------------------------------------------------------------------------
extern "C" void kernel_launch(void* const* d_in, const int* in_sizes, int n_in,
                              void* d_out, int out_size)
{
    const float* x    = (const float*)d_in[0];
    const float* tpr  = (const float*)d_in[1];
    const float* eW1  = (const float*)d_in[2];
    const float* eb1  = (const float*)d_in[3];
    const float* eW2  = (const float*)d_in[4];
    const float* eb2  = (const float*)d_in[5];
    const float* rW1  = (const float*)d_in[6];
    const float* rb1  = (const float*)d_in[7];
    const float* rW2  = (const float*)d_in[8];
    const float* rb2  = (const float*)d_in[9];
    const float* ln_g = (const float*)d_in[10];
    const float* ln_b = (const float*)d_in[11];
    const float* Z    = (const float*)d_in[12];
    float* out = (float*)d_out;

    int B = in_sizes[0] / S;   // 1024

    dim3 g1(32, B / 64);
    k1_gemm_tanh<<<g1, 128>>>(x, eW1, eb1, rW1, rb1, B);

    dim3 g2(B / 32, 4, KSPLIT);
    size_t smem2 = (size_t)(32 * 36 + 32 * 68) * sizeof(float);
    k2_all<<<g2, 256, smem2>>>(eW2, eb2, rW2, rb2, B);

    k3a_contract<<<B * 4, 256>>>(tpr, B);

    k3b_chain<<<B, 64>>>(ln_g, ln_b, Z, out, B);
}

// round 13
// speedup vs baseline: 1.0150x; 1.0150x over previous
#include <cuda_runtime.h>
#include <cuda_fp16.h>
#include <math.h>
#include <stdint.h>

#define S   256
#define Hd  512
#define E   64
#define R   32
#define L   9
#define BMAX 1024
#define KSPLIT 8

typedef unsigned long long u64;

// Scratch (device globals; no allocation allowed)
__device__ float  g_H[4 * BMAX * Hd];      // tanh(x@W1+b1) for {e0, r0, r1, r2}
__device__ float  g_e02[KSPLIT * BMAX * E];     // split-K partials of e0
__device__ float  g_r2[KSPLIT * 3 * BMAX * R];  // split-K partials of r
__device__ __half g_A1h[(size_t)BMAX * E * E];  // A1[b][e][f] fp16
__device__ __half g_A2h[(size_t)BMAX * E * E];  // A2[b][e][f] fp16
__device__ float  g_v1p[(size_t)BMAX * 4 * E];  // per-quarter partials of v1

// ---------------------------------------------------------------------------
// Packed f32x2 helpers (Blackwell FFMA2)
// ---------------------------------------------------------------------------
__device__ __forceinline__ u64 pk2(float x, float y) {
    u64 r;
    asm("mov.b64 %0, {%1, %2};" : "=l"(r) : "f"(x), "f"(y));
    return r;
}
__device__ __forceinline__ void fma2(u64& d, u64 a, u64 b) {
    asm("fma.rn.f32x2 %0, %1, %2, %0;" : "+l"(d) : "l"(a), "l"(b));
}
__device__ __forceinline__ u64 mul2(u64 a, u64 b) {
    u64 d;
    asm("mul.rn.f32x2 %0, %1, %2;" : "=l"(d) : "l"(a), "l"(b));
    return d;
}
__device__ __forceinline__ float2 upk(u64 v) {
    float2 f;
    asm("mov.b64 {%0, %1}, %2;" : "=f"(f.x), "=f"(f.y) : "l"(v));
    return f;
}

// ---------------------------------------------------------------------------
// Tensor-core helpers
// ---------------------------------------------------------------------------
__device__ __forceinline__ void ldsm4(uint32_t& r0, uint32_t& r1,
                                      uint32_t& r2, uint32_t& r3, uint32_t a) {
    asm volatile("ldmatrix.sync.aligned.m8n8.x4.shared.b16 {%0,%1,%2,%3},[%4];"
                 : "=r"(r0), "=r"(r1), "=r"(r2), "=r"(r3) : "r"(a));
}
__device__ __forceinline__ void ldsm4t(uint32_t& r0, uint32_t& r1,
                                       uint32_t& r2, uint32_t& r3, uint32_t a) {
    asm volatile("ldmatrix.sync.aligned.m8n8.x4.trans.shared.b16 {%0,%1,%2,%3},[%4];"
                 : "=r"(r0), "=r"(r1), "=r"(r2), "=r"(r3) : "r"(a));
}
__device__ __forceinline__ void mma16816(float* c,
    uint32_t a0, uint32_t a1, uint32_t a2, uint32_t a3,
    uint32_t b0, uint32_t b1) {
    asm volatile(
        "mma.sync.aligned.m16n8k16.row.col.f32.f16.f16.f32 "
        "{%0,%1,%2,%3},{%4,%5,%6,%7},{%8,%9},{%0,%1,%2,%3};"
        : "+f"(c[0]), "+f"(c[1]), "+f"(c[2]), "+f"(c[3])
        : "r"(a0), "r"(a1), "r"(a2), "r"(a3), "r"(b0), "r"(b1));
}

// ---------------------------------------------------------------------------
// Kernel 1: H = tanh(x @ W1 + b1) via fp16 tensor cores, fp32 accumulate.
// PROVEN round-10 config (~13us): 64x64 CTA tile, 128 threads, K-chunk 32,
// double-buffered half smem.
// ---------------------------------------------------------------------------
__global__ __launch_bounds__(128) void k1_gemm_tanh(
    const float* __restrict__ x,
    const float* __restrict__ eW1, const float* __restrict__ eb1,
    const float* __restrict__ rW1, const float* __restrict__ rb1,
    int B)
{
    const int bn = blockIdx.x;
    const int bm = blockIdx.y;
    const int m  = bn >> 3;
    const int cb = (bn & 7) * 64;
    const float* W    = (m == 0) ? eW1 : (rW1 + (size_t)(m - 1) * S * Hd);
    const float* bias = (m == 0) ? eb1 : (rb1 + (size_t)(m - 1) * Hd);

    constexpr int AST = 40;
    constexpr int BST = 72;
    __shared__ __half Asm[2][64 * AST];
    __shared__ __half Bsm[2][32 * BST];

    const int tid  = threadIdx.x;
    const int warp = tid >> 5;
    const int lane = tid & 31;
    const int rowBase = bm * 64;
    const int warpM   = warp * 16;

    float acc[8][4];
    #pragma unroll
    for (int j = 0; j < 8; j++)
        #pragma unroll
        for (int i = 0; i < 4; i++) acc[j][i] = 0.0f;

    const uint32_t smA[2] = {
        (uint32_t)__cvta_generic_to_shared(&Asm[0][0]),
        (uint32_t)__cvta_generic_to_shared(&Asm[1][0]) };
    const uint32_t smB[2] = {
        (uint32_t)__cvta_generic_to_shared(&Bsm[0][0]),
        (uint32_t)__cvta_generic_to_shared(&Bsm[1][0]) };

    const int a_frow = warpM + (lane & 7) + ((lane >> 3) & 1) * 8;
    const int a_fcol = (lane >> 4) << 3;
    const int b_frow = (lane & 7) + ((lane >> 3) & 1) * 8;
    const int b_fcol = (lane >> 4) << 3;

    float4 av[4], wv[4];
    #pragma unroll
    for (int i = 0; i < 4; i++) {
        int t = tid + i * 128;
        av[i] = *(const float4*)&x[(size_t)(rowBase + (t >> 3)) * S + (t & 7) * 4];
        wv[i] = *(const float4*)&W[(size_t)(t >> 4) * Hd + cb + (t & 15) * 4];
    }
    int buf = 0;
    #pragma unroll
    for (int i = 0; i < 4; i++) {
        int t = tid + i * 128;
        __half2 ha0 = __floats2half2_rn(av[i].x, av[i].y);
        __half2 ha1 = __floats2half2_rn(av[i].z, av[i].w);
        uint2 ua; ua.x = *(uint32_t*)&ha0; ua.y = *(uint32_t*)&ha1;
        *(uint2*)&Asm[0][(t >> 3) * AST + (t & 7) * 4] = ua;
        __half2 hb0 = __floats2half2_rn(wv[i].x, wv[i].y);
        __half2 hb1 = __floats2half2_rn(wv[i].z, wv[i].w);
        uint2 ub; ub.x = *(uint32_t*)&hb0; ub.y = *(uint32_t*)&hb1;
        *(uint2*)&Bsm[0][(t >> 4) * BST + (t & 15) * 4] = ub;
    }
    __syncthreads();

    for (int c = 0; c < 8; c++) {
        if (c < 7) {
            const int k0 = (c + 1) * 32;
            #pragma unroll
            for (int i = 0; i < 4; i++) {
                int t = tid + i * 128;
                av[i] = *(const float4*)&x[(size_t)(rowBase + (t >> 3)) * S + k0 + (t & 7) * 4];
                wv[i] = *(const float4*)&W[(size_t)(k0 + (t >> 4)) * Hd + cb + (t & 15) * 4];
            }
        }
        #pragma unroll
        for (int kk = 0; kk < 32; kk += 16) {
            uint32_t a0, a1, a2, a3;
            ldsm4(a0, a1, a2, a3,
                  smA[buf] + (uint32_t)((a_frow * AST + kk + a_fcol) * 2));
            #pragma unroll
            for (int j = 0; j < 4; j++) {
                uint32_t b0, b1, b2, b3;
                ldsm4t(b0, b1, b2, b3,
                       smB[buf] + (uint32_t)(((kk + b_frow) * BST + j * 16 + b_fcol) * 2));
                mma16816(acc[2 * j],     a0, a1, a2, a3, b0, b1);
                mma16816(acc[2 * j + 1], a0, a1, a2, a3, b2, b3);
            }
        }
        if (c < 7) {
            const int nb = buf ^ 1;
            #pragma unroll
            for (int i = 0; i < 4; i++) {
                int t = tid + i * 128;
                __half2 ha0 = __floats2half2_rn(av[i].x, av[i].y);
                __half2 ha1 = __floats2half2_rn(av[i].z, av[i].w);
                uint2 ua; ua.x = *(uint32_t*)&ha0; ua.y = *(uint32_t*)&ha1;
                *(uint2*)&Asm[nb][(t >> 3) * AST + (t & 7) * 4] = ua;
                __half2 hb0 = __floats2half2_rn(wv[i].x, wv[i].y);
                __half2 hb1 = __floats2half2_rn(wv[i].z, wv[i].w);
                uint2 ub; ub.x = *(uint32_t*)&hb0; ub.y = *(uint32_t*)&hb1;
                *(uint2*)&Bsm[nb][(t >> 4) * BST + (t & 15) * 4] = ub;
            }
            __syncthreads();
            buf = nb;
        }
    }

    const int gid = lane >> 2, tig = lane & 3;
    const int r0 = rowBase + warpM + gid;
    #pragma unroll
    for (int j = 0; j < 8; j++) {
        const int col = cb + j * 8 + tig * 2;
        const float b0v = bias[col], b1v = bias[col + 1];
        float2 o0 = make_float2(tanhf(acc[j][0] + b0v), tanhf(acc[j][1] + b1v));
        float2 o1 = make_float2(tanhf(acc[j][2] + b0v), tanhf(acc[j][3] + b1v));
        *(float2*)&g_H[((size_t)m * B + r0)     * Hd + col] = o0;
        *(float2*)&g_H[((size_t)m * B + r0 + 8) * Hd + col] = o1;
    }
}

// ---------------------------------------------------------------------------
// Kernel 2: layer2 GEMM with split-K 8 (chunks of 64). 1024 CTAs for latency
// hiding on this skinny GEMM. Partials summed in k3a loaders. (round-11, kept)
// ---------------------------------------------------------------------------
template<int O>
__device__ __forceinline__ void k2_body(
    const float* __restrict__ Hb, const float* __restrict__ W2,
    const float* __restrict__ bias, float* __restrict__ outp,
    int B, int kbeg, float* sm)
{
    constexpr int TX = O / 4;
    constexpr int RT = 32 * TX / 256;
    float* Hs = sm;
    float* Ws = sm + 32 * 36;

    const int tid = threadIdx.x;
    const int rowBase = blockIdx.x * 32;
    const int tx = tid % TX;
    const int ty = tid / TX;

    const int h_row = tid >> 3;
    const int h_q   = tid & 7;

    float acc[RT][4];
    #pragma unroll
    for (int i = 0; i < RT; i++)
        #pragma unroll
        for (int j = 0; j < 4; j++) acc[i][j] = 0.0f;

    for (int k0 = kbeg; k0 < kbeg + (Hd / KSPLIT); k0 += 32) {
        float4 hv = *(const float4*)&Hb[(size_t)(rowBase + h_row) * Hd + k0 + h_q * 4];
        float4 wv[2];
        #pragma unroll
        for (int it = 0; it < (8 * O) / 256; it++) {
            int i = tid + it * 256;
            int k  = i / TX;
            int n4 = i % TX;
            wv[it] = *(const float4*)&W2[(size_t)(k0 + k) * O + n4 * 4];
        }
        __syncthreads();
        Hs[(h_q * 4 + 0) * 36 + h_row] = hv.x;
        Hs[(h_q * 4 + 1) * 36 + h_row] = hv.y;
        Hs[(h_q * 4 + 2) * 36 + h_row] = hv.z;
        Hs[(h_q * 4 + 3) * 36 + h_row] = hv.w;
        #pragma unroll
        for (int it = 0; it < (8 * O) / 256; it++) {
            int i = tid + it * 256;
            int k  = i / TX;
            int n4 = i % TX;
            *(float4*)&Ws[k * (O + 4) + n4 * 4] = wv[it];
        }
        __syncthreads();
        #pragma unroll
        for (int kk = 0; kk < 32; kk++) {
            float a[RT];
            #pragma unroll
            for (int i = 0; i < RT; i++) a[i] = Hs[kk * 36 + ty * RT + i];
            float4 w = *(const float4*)&Ws[kk * (O + 4) + tx * 4];
            #pragma unroll
            for (int i = 0; i < RT; i++) {
                acc[i][0] += a[i] * w.x;
                acc[i][1] += a[i] * w.y;
                acc[i][2] += a[i] * w.z;
                acc[i][3] += a[i] * w.w;
            }
        }
    }

    float bv[4];
    #pragma unroll
    for (int j = 0; j < 4; j++) bv[j] = bias ? bias[tx * 4 + j] : 0.0f;
    #pragma unroll
    for (int i = 0; i < RT; i++) {
        int row = rowBase + ty * RT + i;
        #pragma unroll
        for (int j = 0; j < 4; j++)
            outp[(size_t)row * O + tx * 4 + j] = acc[i][j] + bv[j];
    }
}

__global__ __launch_bounds__(256) void k2_all(
    const float* __restrict__ eW2, const float* __restrict__ eb2,
    const float* __restrict__ rW2, const float* __restrict__ rb2, int B)
{
    extern __shared__ float sm2[];
    const int kz   = blockIdx.z;
    const int kbeg = kz * (Hd / KSPLIT);
    if (blockIdx.y == 0) {
        k2_body<64>(g_H, eW2, kz ? nullptr : eb2,
                    g_e02 + (size_t)kz * B * E, B, kbeg, sm2);
    } else {
        int km = blockIdx.y - 1;
        k2_body<32>(g_H + (size_t)(1 + km) * B * Hd,
                    rW2 + (size_t)km * Hd * R, kz ? nullptr : (rb2 + km * R),
                    g_r2 + ((size_t)kz * 3 + km) * B * R,
                    B, kbeg, sm2);
    }
}

// ---------------------------------------------------------------------------
// Kernel 3a: streaming contraction (proven ~6.6 TB/s config). One CTA per
// (batch, e-quarter of 16), 256 threads, buf[8].
// ---------------------------------------------------------------------------
__global__ __launch_bounds__(256) void k3a_contract(
    const float* __restrict__ tpr, int B)
{
    __shared__ float2 srv2[96];
    __shared__ float  se0[16];
    __shared__ float  stmp[8 * 64];

    const int b = blockIdx.x >> 2;
    const int q = blockIdx.x & 3;
    const int tid = threadIdx.x;

    if (tid < 96) {
        const int k = tid >> 5, j = tid & 31;
        float v = 0.0f;
        #pragma unroll
        for (int kz = 0; kz < KSPLIT; kz++)
            v += g_r2[(((size_t)kz * 3 + k) * B + b) * R + j];
        srv2[tid] = make_float2(v, v);
    }
    if (tid < 16) {
        int e = q * 16 + tid;
        float v = 0.0f;
        #pragma unroll
        for (int kz = 0; kz < KSPLIT; kz++)
            v += g_e02[((size_t)kz * B + b) * E + e];
        se0[tid] = v;
    }
    __syncthreads();

    const int el = tid >> 4;
    const int e  = q * 16 + el;
    const int f4 = tid & 15;
    const float4* p = (const float4*)tpr + ((size_t)b * E + e) * (R * 16) + f4;
    const u64 pe = pk2(se0[el], se0[el]);

    u64 v01 = 0, v23 = 0, a10 = 0, a11 = 0, a20 = 0, a21 = 0;
    #pragma unroll 1
    for (int rb = 0; rb < 4; rb++) {
        float4 buf[8];
        #pragma unroll
        for (int u = 0; u < 8; u++)
            buf[u] = __ldcs(&p[(size_t)(rb * 8 + u) * 16]);
        #pragma unroll
        for (int u = 0; u < 8; u++) {
            const int r = rb * 8 + u;
            u64 t01 = pk2(buf[u].x, buf[u].y);
            u64 t23 = pk2(buf[u].z, buf[u].w);
            u64 c0 = *(u64*)&srv2[r];
            u64 c1 = *(u64*)&srv2[32 + r];
            u64 c2 = *(u64*)&srv2[64 + r];
            u64 ce = mul2(pe, c0);
            fma2(v01, ce, t01); fma2(v23, ce, t23);
            fma2(a10, c1, t01); fma2(a11, c1, t23);
            fma2(a20, c2, t01); fma2(a21, c2, t23);
        }
    }

    {
        __half2 h0 = __float22half2_rn(upk(a10));
        __half2 h1 = __float22half2_rn(upk(a11));
        *(__half2*)&g_A1h[(size_t)b * E * E + e * E + f4 * 4]     = h0;
        *(__half2*)&g_A1h[(size_t)b * E * E + e * E + f4 * 4 + 2] = h1;
        h0 = __float22half2_rn(upk(a20));
        h1 = __float22half2_rn(upk(a21));
        *(__half2*)&g_A2h[(size_t)b * E * E + e * E + f4 * 4]     = h0;
        *(__half2*)&g_A2h[(size_t)b * E * E + e * E + f4 * 4 + 2] = h1;
    }

    {
        float2 a = upk(v01), c = upk(v23);
        a.x += __shfl_xor_sync(0xffffffffu, a.x, 16);
        a.y += __shfl_xor_sync(0xffffffffu, a.y, 16);
        c.x += __shfl_xor_sync(0xffffffffu, c.x, 16);
        c.y += __shfl_xor_sync(0xffffffffu, c.y, 16);
        if ((tid & 31) < 16) {
            const int w = tid >> 5;
            *(float4*)&stmp[w * 64 + (tid & 15) * 4] = make_float4(a.x, a.y, c.x, c.y);
        }
    }
    __syncthreads();
    if (tid < 64) {
        float s = 0.0f;
        #pragma unroll
        for (int w = 0; w < 8; w++) s += stmp[w * 64 + tid];
        g_v1p[((size_t)b * 4 + q) * E + tid] = s;
    }
}

// ---------------------------------------------------------------------------
// Kernel 3b: chain, ONE WARP per batch (proven round-10 config, 8.5us).
// Thread t owns f = 2t, 2t+1 in regs; no smem, no barriers; deterministic
// fixed-order shuffles. A1/A2 read directly from L2 as __half2.
// ---------------------------------------------------------------------------
__global__ __launch_bounds__(32) void k3b_chain(
    const float* __restrict__ ln_g, const float* __restrict__ ln_b,
    const float* __restrict__ Z,
    float* __restrict__ out, int B)
{
    const int b = blockIdx.x;
    const int t = threadIdx.x;
    const int f0 = 2 * t;

    float x0 = 0.0f, x1 = 0.0f;
    #pragma unroll
    for (int q = 0; q < 4; q++) {
        float2 v = *(const float2*)&g_v1p[((size_t)b * 4 + q) * E + f0];
        x0 += v.x; x1 += v.y;
    }

    const __half* A1 = g_A1h + (size_t)b * E * E;
    const __half* A2 = g_A2h + (size_t)b * E * E;
    float sum0 = 0.0f, sum1 = 0.0f;

    #pragma unroll
    for (int step = 0; step < 3; step++) {
        float v0, v1v;
        if (step == 0) {
            v0 = x0; v1v = x1;
        } else {
            const __half* A = (step == 1) ? A1 : A2;
            float a0 = 0.0f, a1 = 0.0f;
            #pragma unroll
            for (int e = 0; e < E; e += 2) {
                float c0 = __shfl_sync(0xffffffffu, x0, e >> 1);
                float c1 = __shfl_sync(0xffffffffu, x1, e >> 1);
                float2 w0 = __half22float2(*(const __half2*)&A[e * E + f0]);
                float2 w1 = __half22float2(*(const __half2*)&A[(e + 1) * E + f0]);
                a0 += c0 * w0.x + c1 * w1.x;
                a1 += c0 * w0.y + c1 * w1.y;
            }
            v0 = a0; v1v = a1;
        }
        float s1 = v0 + v1v, s2 = v0 * v0 + v1v * v1v;
        #pragma unroll
        for (int o = 16; o; o >>= 1) {
            s1 += __shfl_xor_sync(0xffffffffu, s1, o);
            s2 += __shfl_xor_sync(0xffffffffu, s2, o);
        }
        float mu  = s1 * (1.0f / 64.0f);
        float var = s2 * (1.0f / 64.0f) - mu * mu;
        float inv = rsqrtf(var + 1e-6f);
        x0 = ln_g[step * E + f0]     * (v0  - mu) * inv + ln_b[step * E + f0];
        x1 = ln_g[step * E + f0 + 1] * (v1v - mu) * inv + ln_b[step * E + f0 + 1];
        sum0 += x0; sum1 += x1;
    }

    #pragma unroll
    for (int l = 0; l < L; l++) {
        float p = sum0 * Z[f0 * L + l] + sum1 * Z[(f0 + 1) * L + l];
        #pragma unroll
        for (int o = 16; o; o >>= 1)
            p += __shfl_xor_sync(0xffffffffu, p, o);
        if (t == 0) out[(size_t)b * L + l] = p;
    }
}

// ---------------------------------------------------------------------------
extern "C" void kernel_launch(void* const* d_in, const int* in_sizes, int n_in,
                              void* d_out, int out_size)
{
    const float* x    = (const float*)d_in[0];
    const float* tpr  = (const float*)d_in[1];
    const float* eW1  = (const float*)d_in[2];
    const float* eb1  = (const float*)d_in[3];
    const float* eW2  = (const float*)d_in[4];
    const float* eb2  = (const float*)d_in[5];
    const float* rW1  = (const float*)d_in[6];
    const float* rb1  = (const float*)d_in[7];
    const float* rW2  = (const float*)d_in[8];
    const float* rb2  = (const float*)d_in[9];
    const float* ln_g = (const float*)d_in[10];
    const float* ln_b = (const float*)d_in[11];
    const float* Z    = (const float*)d_in[12];
    float* out = (float*)d_out;

    int B = in_sizes[0] / S;   // 1024

    dim3 g1(32, B / 64);
    k1_gemm_tanh<<<g1, 128>>>(x, eW1, eb1, rW1, rb1, B);

    dim3 g2(B / 32, 4, KSPLIT);
    size_t smem2 = (size_t)(32 * 36 + 32 * 68) * sizeof(float);
    k2_all<<<g2, 256, smem2>>>(eW2, eb2, rW2, rb2, B);

    k3a_contract<<<B * 4, 256>>>(tpr, B);

    k3b_chain<<<B, 32>>>(ln_g, ln_b, Z, out, B);
}